// round 7
// baseline (speedup 1.0000x reference)
#include <cuda_runtime.h>

#define NB    1024      // batch
#define NS    32        // neighbors per hop
#define DIM   64
#define NREL  237
#define NRELP 238
#define NENTP 14542     // NENT + 1
#define WCS   256       // padded row stride for folded output weights

// ---------------- scratch (device globals; no allocation allowed) ----------
__device__ __align__(16) float g_R[NRELP * DIM];       // relf @ W_agg0 (row 237 = 0)
__device__ __align__(16) float g_S[NENTP * DIM];       // unmasked hop-2 sums per entity
__device__ __align__(16) float g_Wc[2 * DIM * WCS];    // W_agg1 @ W_out halves, padded rows
__device__ __align__(16) float g_W4p[DIM * WCS];       // mW4 padded to 1KB rows
__device__ __align__(16) float g_bc[NREL];             // b_agg1 @ (Wtop+Wbot) + b_out
__device__ __align__(16) float g_A[DIM * DIM];         // W_agg1 @ mW1[0:237]
__device__ __align__(16) float g_d[DIM];               // b_agg1 @ mW1[0:237] + mb1
__device__ __align__(16) float g_pre[2 * NB * DIM];    // masked-mean hidden per side
__device__ __align__(16) float g_h3[NB * DIM];         // MLP hidden after layer 3

__device__ __forceinline__ float selu_f(float x) {
    const float sc  = 1.0507009873554805f;
    const float asc = 1.7580993408473766f;   // sc * alpha
    return x > 0.f ? sc * x : asc * expm1f(x);
}

// ---------------- kernel 0: per-launch weight folding ----------------------
__global__ __launch_bounds__(256) void k_fold(
    const float* __restrict__ relf, const float* __restrict__ W0,
    const float* __restrict__ W1,   const float* __restrict__ b1,
    const float* __restrict__ Wout, const float* __restrict__ bout,
    const float* __restrict__ mW1,  const float* __restrict__ mb1,
    const float* __restrict__ mW4)
{
    int bid = blockIdx.x, tid = threadIdx.x;
    if (bid < NRELP) {                       // R = relf @ W_agg0  (row 237 zero)
        if (tid < DIM) {
            float a0 = 0.f, a1 = 0.f, a2 = 0.f, a3 = 0.f;
            if (bid < NREL) {
                #pragma unroll
                for (int k = 0; k < DIM; k += 4) {
                    a0 += relf[bid * DIM + k]     * W0[(k)     * DIM + tid];
                    a1 += relf[bid * DIM + k + 1] * W0[(k + 1) * DIM + tid];
                    a2 += relf[bid * DIM + k + 2] * W0[(k + 2) * DIM + tid];
                    a3 += relf[bid * DIM + k + 3] * W0[(k + 3) * DIM + tid];
                }
            }
            g_R[bid * DIM + tid] = (a0 + a1) + (a2 + a3);
        }
    } else if (bid < NRELP + 128) {          // Wc[s][i][:] = W_agg1[i,:] @ W_out half
        int idx = bid - NRELP;
        int s = idx >> 6, i = idx & 63;
        if (tid < NREL) {
            float a0 = 0.f, a1 = 0.f, a2 = 0.f, a3 = 0.f;
            const float* w1r = W1 + i * NREL;
            const float* wo  = Wout + s * NREL * NREL;
            int k = 0;
            for (; k + 3 < NREL; k += 4) {
                a0 += w1r[k]     * wo[(k)     * NREL + tid];
                a1 += w1r[k + 1] * wo[(k + 1) * NREL + tid];
                a2 += w1r[k + 2] * wo[(k + 2) * NREL + tid];
                a3 += w1r[k + 3] * wo[(k + 3) * NREL + tid];
            }
            for (; k < NREL; k++) a0 += w1r[k] * wo[k * NREL + tid];
            g_Wc[s * DIM * WCS + i * WCS + tid] = (a0 + a1) + (a2 + a3);
        }
    } else if (bid < NRELP + 128 + 64) {     // A[i][:] = W_agg1[i,:] @ mW1[0:237]
        int i = bid - NRELP - 128;
        if (tid < DIM) {
            float a0 = 0.f, a1 = 0.f, a2 = 0.f, a3 = 0.f;
            const float* w1r = W1 + i * NREL;
            int k = 0;
            for (; k + 3 < NREL; k += 4) {
                a0 += w1r[k]     * mW1[(k)     * DIM + tid];
                a1 += w1r[k + 1] * mW1[(k + 1) * DIM + tid];
                a2 += w1r[k + 2] * mW1[(k + 2) * DIM + tid];
                a3 += w1r[k + 3] * mW1[(k + 3) * DIM + tid];
            }
            for (; k < NREL; k++) a0 += w1r[k] * mW1[k * DIM + tid];
            g_A[i * DIM + tid] = (a0 + a1) + (a2 + a3);
        }
    } else if (bid < NRELP + 128 + 64 + 64) { // padded copy of mW4
        int kk = bid - (NRELP + 128 + 64);
        if (tid < NREL) g_W4p[kk * WCS + tid] = mW4[kk * NREL + tid];
    } else {                                 // bias vectors
        if (tid < NREL) {
            float acc = bout[tid];
            for (int k = 0; k < NREL; k++)
                acc += b1[k] * (Wout[k * NREL + tid] + Wout[(k + NREL) * NREL + tid]);
            g_bc[tid] = acc;
        }
        if (tid < DIM) {
            float acc = mb1[tid];
            for (int k = 0; k < NREL; k++)
                acc += b1[k] * mW1[k * DIM + tid];
            g_d[tid] = acc;
        }
    }
}

// ---------------- kernel 1: unmasked hop-2 sums per entity -----------------
__global__ __launch_bounds__(256) void k_S(
    const int* __restrict__ entity2edges, const int* __restrict__ edge2relation)
{
    int w = threadIdx.x >> 5, lane = threadIdx.x & 31;
    int ent = blockIdx.x * 8 + w;
    if (ent >= NENTP) return;
    int e = entity2edges[ent * NS + lane];        // coalesced
    int r = edge2relation[e];                     // scattered gather
    const float2* R2 = (const float2*)g_R;
    float a0 = 0.f, a1 = 0.f, b0 = 0.f, b1 = 0.f;
    #pragma unroll
    for (int j = 0; j < 32; j += 2) {             // two independent chains
        int rj0 = __shfl_sync(0xffffffffu, r, j);
        int rj1 = __shfl_sync(0xffffffffu, r, j + 1);
        float2 f0 = R2[rj0 * 32 + lane];
        float2 f1 = R2[rj1 * 32 + lane];
        a0 += f0.x; a1 += f0.y;
        b0 += f1.x; b1 += f1.y;
    }
    ((float2*)g_S)[ent * 32 + lane] = make_float2(a0 + b0, a1 + b1);
}

// ---------------- kernel 2: per-(b, side) aggregation via S correction -----
__global__ __launch_bounds__(256) void k_side(
    const int* __restrict__ entity_pairs, const int* __restrict__ train_edges,
    const int* __restrict__ entity2edges, const int* __restrict__ edge2entities,
    const int* __restrict__ edge2relation, const float* __restrict__ b_agg0)
{
    int w = threadIdx.x >> 5, lane = threadIdx.x & 31;
    int task = blockIdx.x * 8 + w;               // [0, 2*NB)
    int b = task >> 1, side = task & 1;

    int te  = train_edges[b];
    int ent = entity_pairs[b * 2 + side];
    int e1   = entity2edges[ent * NS + lane];    // coalesced
    float m1 = (e1 != te) ? 1.f : 0.f;
    int r1   = edge2relation[e1];                // scattered
    int ent2 = edge2entities[e1];                // scattered
    int r_te = edge2relation[te];

    const float2* R2 = (const float2*)g_R;
    const float2* S2 = (const float2*)g_S;
    float2 corr = R2[r_te * 32 + lane];
    float bias0 = b_agg0[2 * lane], bias1 = b_agg0[2 * lane + 1];
    float p0 = 0.f, p1 = 0.f, q0 = 0.f, q1 = 0.f;

    #pragma unroll 2
    for (int si = 0; si < 32; si += 2) {
        int entA = __shfl_sync(0xffffffffu, ent2, si);
        int entB = __shfl_sync(0xffffffffu, ent2, si + 1);
        int e2A  = entity2edges[entA * NS + lane];
        int e2B  = entity2edges[entB * NS + lane];
        float2 SA = S2[entA * 32 + lane];
        float2 SB = S2[entB * 32 + lane];
        unsigned balA = __ballot_sync(0xffffffffu, e2A == te);
        unsigned balB = __ballot_sync(0xffffffffu, e2B == te);
        float cntA = (float)__popc(balA);
        float cntB = (float)__popc(balB);
        int r1A = __shfl_sync(0xffffffffu, r1, si);
        int r1B = __shfl_sync(0xffffffffu, r1, si + 1);
        float2 eA = R2[r1A * 32 + lane];
        float2 eB = R2[r1B * 32 + lane];
        float mA = __shfl_sync(0xffffffffu, m1, si);
        float mB = __shfl_sync(0xffffffffu, m1, si + 1);
        p0 += mA * fmaxf((SA.x - cntA * corr.x) * (1.f / NS) + eA.x + bias0, 0.f);
        p1 += mA * fmaxf((SA.y - cntA * corr.y) * (1.f / NS) + eA.y + bias1, 0.f);
        q0 += mB * fmaxf((SB.x - cntB * corr.x) * (1.f / NS) + eB.x + bias0, 0.f);
        q1 += mB * fmaxf((SB.y - cntB * corr.y) * (1.f / NS) + eB.y + bias1, 0.f);
    }
    ((float2*)g_pre)[(side * NB + b) * 32 + lane] =
        make_float2((p0 + q0) * (1.f / NS), (p1 + q1) * (1.f / NS));
}

// ---------------- kernel 3: MLP layers 1-3, 2 batches/block, 4-way k-split -
// 512 threads: q = k-quarter (0-3), i = batch (0-1), j = dim (0-63)
__global__ __launch_bounds__(512) void k_mlp3(
    const float* __restrict__ t_in, const float* __restrict__ eps,
    const float* __restrict__ mW1,
    const float* __restrict__ mW2, const float* __restrict__ mb2,
    const float* __restrict__ mW3, const float* __restrict__ mb3)
{
    __shared__ __align__(16) float s_pm[DIM * 2];   // [kk][b]
    __shared__ __align__(16) float s_ha[DIM * 2];
    __shared__ float s_eps[2][240];
    __shared__ float s_part[512];

    int tid = threadIdx.x;
    int q = tid >> 7, r = tid & 127;
    int i = r >> 6, j = r & 63;
    int b0 = blockIdx.x * 2;
    float ti = t_in[b0 + i];

    if (q == 0) {
        float q0v = g_pre[(b0 + i) * DIM + j];
        float q1v = g_pre[(NB + b0 + i) * DIM + j];
        s_pm[j * 2 + i] = (1.f - ti) * q0v + ti * q1v;
    }
    {   // stage eps: 512 threads cover 2*237
        int c = tid;
        if (c < NREL) s_eps[0][c] = eps[b0 * NREL + c];
        else if (c >= 256 && c < 256 + NREL)
            s_eps[1][c - 256] = eps[(b0 + 1) * NREL + c - 256];
    }
    __syncthreads();

    // ---- layer 1 partial: pm@A (16 kk) + 0.1*eps@mW1 (60/60/60/57 kk) ----
    {
        int k0 = q * 16;
        float g0 = 0.f, g1 = 0.f, g2 = 0.f, g3 = 0.f;
        #pragma unroll
        for (int kk = k0; kk < k0 + 16; kk += 4) {
            g0 += s_pm[(kk)     * 2 + i] * g_A[(kk)     * DIM + j];
            g1 += s_pm[(kk + 1) * 2 + i] * g_A[(kk + 1) * DIM + j];
            g2 += s_pm[(kk + 2) * 2 + i] * g_A[(kk + 2) * DIM + j];
            g3 += s_pm[(kk + 3) * 2 + i] * g_A[(kk + 3) * DIM + j];
        }
        int eb = q * 60, ee = (q == 3) ? NREL : (eb + 60);
        float e0 = 0.f, e1 = 0.f, e2 = 0.f, e3 = 0.f;
        int kk = eb;
        #pragma unroll 4
        for (; kk + 3 < ee; kk += 4) {
            e0 += s_eps[i][kk]     * mW1[(kk)     * DIM + j];
            e1 += s_eps[i][kk + 1] * mW1[(kk + 1) * DIM + j];
            e2 += s_eps[i][kk + 2] * mW1[(kk + 2) * DIM + j];
            e3 += s_eps[i][kk + 3] * mW1[(kk + 3) * DIM + j];
        }
        for (; kk < ee; kk++) e0 += s_eps[i][kk] * mW1[kk * DIM + j];
        float ps = ((g0 + g1) + (g2 + g3)) + 0.1f * ((e0 + e1) + (e2 + e3));
        if (q == 0) ps += g_d[j] + ti * mW1[NREL * DIM + j];
        s_part[tid] = ps;
    }
    __syncthreads();
    if (q == 0)
        s_ha[j * 2 + i] = selu_f((s_part[tid] + s_part[tid + 128])
                               + (s_part[tid + 256] + s_part[tid + 384]));
    __syncthreads();

    // ---- layer 2 partial (16 kk each) ----
    {
        int k0 = q * 16;
        float n0 = 0.f, n1 = 0.f, n2 = 0.f, n3 = 0.f;
        #pragma unroll
        for (int kk = k0; kk < k0 + 16; kk += 4) {
            n0 += s_ha[(kk)     * 2 + i] * mW2[(kk)     * DIM + j];
            n1 += s_ha[(kk + 1) * 2 + i] * mW2[(kk + 1) * DIM + j];
            n2 += s_ha[(kk + 2) * 2 + i] * mW2[(kk + 2) * DIM + j];
            n3 += s_ha[(kk + 3) * 2 + i] * mW2[(kk + 3) * DIM + j];
        }
        s_part[tid] = (q == 0 ? mb2[j] : 0.f) + (n0 + n1) + (n2 + n3);
    }
    __syncthreads();
    if (q == 0)
        s_pm[j * 2 + i] = selu_f((s_part[tid] + s_part[tid + 128])
                               + (s_part[tid + 256] + s_part[tid + 384]));
    __syncthreads();

    // ---- layer 3 partial ----
    {
        int k0 = q * 16;
        float n0 = 0.f, n1 = 0.f, n2 = 0.f, n3 = 0.f;
        #pragma unroll
        for (int kk = k0; kk < k0 + 16; kk += 4) {
            n0 += s_pm[(kk)     * 2 + i] * mW3[(kk)     * DIM + j];
            n1 += s_pm[(kk + 1) * 2 + i] * mW3[(kk + 1) * DIM + j];
            n2 += s_pm[(kk + 2) * 2 + i] * mW3[(kk + 2) * DIM + j];
            n3 += s_pm[(kk + 3) * 2 + i] * mW3[(kk + 3) * DIM + j];
        }
        s_part[tid] = (q == 0 ? mb3[j] : 0.f) + (n0 + n1) + (n2 + n3);
    }
    __syncthreads();
    if (q == 0)
        g_h3[(b0 + i) * DIM + j] = selu_f((s_part[tid] + s_part[tid + 128])
                                        + (s_part[tid + 256] + s_part[tid + 384]));
}

// ---------------- kernel 4: scores, 2 batches/block ------------------------
// 512 threads: h = half selector (Wc0/Wc1 and W4 k-half), j = out col
__global__ __launch_bounds__(512) void k_score(
    const float* __restrict__ mb4, float* __restrict__ out)
{
    __shared__ __align__(16) float s_q0[DIM * 2];   // [kk][b]
    __shared__ __align__(16) float s_q1[DIM * 2];
    __shared__ __align__(16) float s_h[DIM * 2];
    __shared__ __align__(16) float2 s_po[512];
    __shared__ __align__(16) float2 s_pv[512];

    int tid = threadIdx.x;
    int h = tid >> 8, r = tid & 255;
    int b0 = blockIdx.x * 2;

    {   // stage activations, [kk][b] layout (128 slots per array, 256 threads/h)
        int i = r >> 7, kk = r & 63, sel = (r >> 6) & 1;
        if (i == 0) {
            if (h == 0) { if (!sel) s_q0[kk * 2] = g_pre[b0 * DIM + kk];
                          else      s_q0[kk * 2 + 1] = g_pre[(b0 + 1) * DIM + kk]; }
            else        { if (!sel) s_q1[kk * 2] = g_pre[(NB + b0) * DIM + kk];
                          else      s_q1[kk * 2 + 1] = g_pre[(NB + b0 + 1) * DIM + kk]; }
        } else {
            if (h == 0) { if (!sel) s_h[kk * 2] = g_h3[b0 * DIM + kk];
                          else      s_h[kk * 2 + 1] = g_h3[(b0 + 1) * DIM + kk]; }
        }
    }
    __syncthreads();

    int j = r;
    if (j < NREL) {
        // out partial: h=0 -> bc + q0@Wc0 ; h=1 -> q1@Wc1
        float2 ao = make_float2(0.f, 0.f);
        float2 ao2 = make_float2(0.f, 0.f);
        const float*  W  = g_Wc + h * DIM * WCS + j;
        const float2* q2 = (const float2*)(h ? s_q1 : s_q0);
        #pragma unroll 8
        for (int kk = 0; kk < DIM; kk += 2) {
            float w0 = W[kk * WCS], w1 = W[(kk + 1) * WCS];
            float2 qa = q2[kk], qb = q2[kk + 1];
            ao.x  += qa.x * w0; ao.y  += qa.y * w0;
            ao2.x += qb.x * w1; ao2.y += qb.y * w1;
        }
        ao.x += ao2.x; ao.y += ao2.y;
        if (h == 0) { float bc = g_bc[j]; ao.x += bc; ao.y += bc; }
        s_po[tid] = ao;

        // vt partial: h splits kk 0-31 / 32-63 of W4
        float2 av = make_float2(0.f, 0.f);
        float2 av2 = make_float2(0.f, 0.f);
        const float*  W4 = g_W4p + j;
        const float2* h2 = (const float2*)s_h;
        int k0 = h * 32;
        #pragma unroll 8
        for (int kk = k0; kk < k0 + 32; kk += 2) {
            float w0 = W4[kk * WCS], w1 = W4[(kk + 1) * WCS];
            float2 ha = h2[kk], hb = h2[kk + 1];
            av.x  += ha.x * w0; av.y  += ha.y * w0;
            av2.x += hb.x * w1; av2.y += hb.y * w1;
        }
        av.x += av2.x; av.y += av2.y;
        if (h == 0) { float m = mb4[j]; av.x += m; av.y += m; }
        s_pv[tid] = av;
    }
    __syncthreads();

    if (h == 0 && j < NREL) {
        float2 o1 = s_po[tid], o2 = s_po[tid + 256];
        float2 v1 = s_pv[tid], v2 = s_pv[tid + 256];
        out[(b0 + 0) * NREL + j] = (o1.x + o2.x) * (v1.x + v2.x);
        out[(b0 + 1) * NREL + j] = (o1.y + o2.y) * (v1.y + v2.y);
    }
}

// ---------------- launcher --------------------------------------------------
extern "C" void kernel_launch(void* const* d_in, const int* in_sizes, int n_in,
                              void* d_out, int out_size)
{
    const int*   entity_pairs  = (const int*)d_in[0];
    const int*   train_edges   = (const int*)d_in[1];
    // d_in[2] = labels : dead
    const int*   entity2edges  = (const int*)d_in[3];
    const int*   edge2entities = (const int*)d_in[4];
    const int*   edge2relation = (const int*)d_in[5];
    const float* t             = (const float*)d_in[6];
    const float* eps           = (const float*)d_in[7];
    const float* rel_feat      = (const float*)d_in[8];
    const float* W_agg0        = (const float*)d_in[9];
    const float* b_agg0        = (const float*)d_in[10];
    const float* W_agg1        = (const float*)d_in[11];
    const float* b_agg1        = (const float*)d_in[12];
    const float* W_out         = (const float*)d_in[13];
    const float* b_out         = (const float*)d_in[14];
    const float* mW1           = (const float*)d_in[15];
    const float* mb1           = (const float*)d_in[16];
    const float* mW2           = (const float*)d_in[17];
    const float* mb2           = (const float*)d_in[18];
    const float* mW3           = (const float*)d_in[19];
    const float* mb3           = (const float*)d_in[20];
    const float* mW4           = (const float*)d_in[21];
    const float* mb4           = (const float*)d_in[22];
    float* out = (float*)d_out;

    k_fold<<<NRELP + 128 + 64 + 64 + 1, 256>>>(rel_feat, W_agg0, W_agg1, b_agg1,
                                               W_out, b_out, mW1, mb1, mW4);
    k_S<<<(NENTP + 7) / 8, 256>>>(entity2edges, edge2relation);
    k_side<<<(2 * NB) / 8, 256>>>(entity_pairs, train_edges, entity2edges,
                                  edge2entities, edge2relation, b_agg0);
    k_mlp3<<<NB / 2, 512>>>(t, eps, mW1, mW2, mb2, mW3, mb3);
    k_score<<<NB / 2, 512>>>(mb4, out);
}